// round 1
// baseline (speedup 1.0000x reference)
#include <cuda_runtime.h>

// PTDNet-GCN fused pipeline:
//  1) tiny prep: fold attention MLP into per-node scalars (a,b,cst)
//  2) CSR build: indeg count -> block scan -> fill (src-per-edge, bucketed by col)
//  3) xw = x @ W0 via f32x2 packed-FFMA register-tiled SGEMM
//  4) conv0: per-node warp gather of xw, fused epilogue computes hw=h@W1, u, v
//  5) attention pass: mw per edge (CSR order) + deg1 -> dinv1
//  6) conv1: per-node gather of hw with masked weights -> output

#define N_NODES 100000
#define N_EDGES 1600000
#define IN_DIM  512
#define H0      32
#define H1      8
#define ZETA    1.01f
#define NB_SCAN 98   // ceil(100000/1024)

// ---------------- scratch (static device memory; no allocation) -------------
__device__ float g_xw[N_NODES * H0];      // x @ W0
__device__ float g_hw[N_NODES * H1];      // h @ W1
__device__ int   g_cnt[N_NODES];          // in-degree
__device__ int   g_off[N_NODES + 1];      // CSR offsets
__device__ int   g_cursor[N_NODES];       // fill cursors
__device__ int   g_bsum[NB_SCAN];         // scan block sums
__device__ int   g_src[N_EDGES];          // CSR source node per slot
__device__ float g_mw[N_EDGES];           // masked edge weight (CSR order)
__device__ float g_dinv0[N_NODES];
__device__ float g_dinv1[N_NODES];
__device__ float g_u[N_NODES];            // h . (Wnb @ Watt[:8])
__device__ float g_v[N_NODES];            // h . (Wself @ Watt[8:])
__device__ float g_att_a[H0];
__device__ float g_att_b[H0];
__device__ float g_cst;

// ---------------- helpers ---------------------------------------------------
__device__ __forceinline__ float wred(float x) {
    x += __shfl_xor_sync(0xffffffffu, x, 16);
    x += __shfl_xor_sync(0xffffffffu, x, 8);
    x += __shfl_xor_sync(0xffffffffu, x, 4);
    x += __shfl_xor_sync(0xffffffffu, x, 2);
    x += __shfl_xor_sync(0xffffffffu, x, 1);
    return x;
}

// ---------------- 1) attention folding prep ---------------------------------
__global__ void prep_ab(const float* __restrict__ Wnb, const float* __restrict__ bnb,
                        const float* __restrict__ Wself, const float* __restrict__ bself,
                        const float* __restrict__ Watt, const float* __restrict__ batt) {
    int j = threadIdx.x;  // 32 threads
    float a = 0.f, b = 0.f;
#pragma unroll
    for (int q = 0; q < 8; ++q) {
        a += Wnb[j * 8 + q] * Watt[q];
        b += Wself[j * 8 + q] * Watt[8 + q];
    }
    g_att_a[j] = a;
    g_att_b[j] = b;
    if (j == 0) {
        float c = batt[0];
#pragma unroll
        for (int q = 0; q < 8; ++q) c += bnb[q] * Watt[q] + bself[q] * Watt[8 + q];
        g_cst = c;
    }
}

// ---------------- 2) CSR build ----------------------------------------------
__global__ void zero_cnt() {
    int i = blockIdx.x * blockDim.x + threadIdx.x;
    if (i < N_NODES) g_cnt[i] = 0;
}

__global__ void count_kernel(const int* __restrict__ eidx) {
    int e = blockIdx.x * blockDim.x + threadIdx.x;
    if (e >= N_EDGES) return;
    atomicAdd(&g_cnt[eidx[N_EDGES + e]], 1);   // col = target
}

__global__ __launch_bounds__(1024) void scan1() {
    __shared__ int sm[1024];
    int tid = threadIdx.x;
    int i = blockIdx.x * 1024 + tid;
    int v = (i < N_NODES) ? g_cnt[i] : 0;
    sm[tid] = v;
    __syncthreads();
    for (int o = 1; o < 1024; o <<= 1) {
        int t = (tid >= o) ? sm[tid - o] : 0;
        __syncthreads();
        sm[tid] += t;
        __syncthreads();
    }
    if (i < N_NODES) g_off[i] = sm[tid] - v;       // exclusive within block
    if (tid == 1023) g_bsum[blockIdx.x] = sm[tid]; // block total
}

__global__ void scan2() {
    if (threadIdx.x == 0) {
        int run = 0;
        for (int b = 0; b < NB_SCAN; ++b) {
            int t = g_bsum[b]; g_bsum[b] = run; run += t;
        }
    }
}

__global__ void scan3() {
    int i = blockIdx.x * blockDim.x + threadIdx.x;
    if (i >= N_NODES) return;
    int o = g_off[i] + g_bsum[i >> 10];
    g_off[i] = o;
    g_cursor[i] = o;
    g_dinv0[i] = rsqrtf((float)g_cnt[i] + 1.0f);
    if (i == 0) g_off[N_NODES] = N_EDGES;
}

__global__ void fill_kernel(const int* __restrict__ eidx) {
    int e = blockIdx.x * blockDim.x + threadIdx.x;
    if (e >= N_EDGES) return;
    int r = eidx[e];
    int c = eidx[N_EDGES + e];
    int pos = atomicAdd(&g_cursor[c], 1);
    g_src[pos] = r;
}

// ---------------- 3) xw = x @ W0  (f32x2 packed FFMA SGEMM) -----------------
// Block: 128 nodes x 32 cols, 128 threads, each thread 4 nodes x 8 cols (4 f32x2 pairs).
__global__ __launch_bounds__(128) void gemm_xw(const float* __restrict__ x,
                                               const float* __restrict__ W0) {
    __shared__ float xs[128 * 33];   // pad 33 -> conflict-free strided reads
    __shared__ float ws[32 * 32];
    int tid = threadIdx.x;
    int row0 = blockIdx.x * 128;
    int r0 = (tid >> 2) * 4;         // 0..124
    int c0 = (tid & 3) * 8;          // 0,8,16,24

    unsigned long long acc[4][4];
#pragma unroll
    for (int r = 0; r < 4; ++r)
#pragma unroll
        for (int c = 0; c < 4; ++c) acc[r][c] = 0ull;

    for (int k0 = 0; k0 < IN_DIM; k0 += 32) {
        // load x tile [128][32] (scalar smem stores keep banks clean with pad 33)
#pragma unroll
        for (int it = 0; it < 8; ++it) {
            int idx = tid + it * 128;        // 0..1023 float4 slots
            int rr = idx >> 3;
            int cc = (idx & 7) << 2;
            int grow = row0 + rr;
            float4 v = make_float4(0.f, 0.f, 0.f, 0.f);
            if (grow < N_NODES)
                v = *(const float4*)(x + (size_t)grow * IN_DIM + k0 + cc);
            float* d = xs + rr * 33 + cc;
            d[0] = v.x; d[1] = v.y; d[2] = v.z; d[3] = v.w;
        }
        // load W chunk [32][32] (flat contiguous)
#pragma unroll
        for (int it = 0; it < 2; ++it) {
            int idx = tid + it * 128;
            *(float4*)(ws + idx * 4) = *(const float4*)(W0 + k0 * 32 + idx * 4);
        }
        __syncthreads();

#pragma unroll
        for (int kk = 0; kk < 32; ++kk) {
            unsigned long long xv[4];
#pragma unroll
            for (int r = 0; r < 4; ++r) {
                float xf = xs[(r0 + r) * 33 + kk];
                asm("mov.b64 %0, {%1, %1};" : "=l"(xv[r]) : "f"(xf));
            }
            const unsigned long long* wrow =
                (const unsigned long long*)(ws + kk * 32 + c0);
#pragma unroll
            for (int c = 0; c < 4; ++c) {
                unsigned long long wv = wrow[c];
#pragma unroll
                for (int r = 0; r < 4; ++r)
                    asm("fma.rn.f32x2 %0, %1, %2, %0;"
                        : "+l"(acc[r][c]) : "l"(xv[r]), "l"(wv));
            }
        }
        __syncthreads();
    }

#pragma unroll
    for (int r = 0; r < 4; ++r) {
        int grow = row0 + r0 + r;
        if (grow < N_NODES) {
            unsigned long long* o = (unsigned long long*)(g_xw + grow * 32 + c0);
#pragma unroll
            for (int c = 0; c < 4; ++c) o[c] = acc[r][c];
        }
    }
}

// ---------------- 4) conv0 + fused (hw, u, v) -------------------------------
// One warp per node; lane = feature column j (32 features).
__global__ __launch_bounds__(256) void conv0_kernel(const float* __restrict__ b0,
                                                    const float* __restrict__ W1) {
    int warp = (blockIdx.x * blockDim.x + threadIdx.x) >> 5;
    int j = threadIdx.x & 31;
    if (warp >= N_NODES) return;
    int node = warp;
    int s = g_off[node], e = g_off[node + 1];
    float dc = g_dinv0[node];
    float sum = dc * g_xw[node * 32 + j];   // self-loop term (gets *dc below)

    for (int base = s; base < e; base += 32) {
        int p = base + j;
        int rr = 0; float dd = 0.f;
        if (p < e) { rr = g_src[p]; dd = g_dinv0[rr]; }
        int cnt = min(32, e - base);
        int t = 0;
        for (; t + 4 <= cnt; t += 4) {
            int   ra = __shfl_sync(0xffffffffu, rr, t);
            float da = __shfl_sync(0xffffffffu, dd, t);
            int   rb = __shfl_sync(0xffffffffu, rr, t + 1);
            float db = __shfl_sync(0xffffffffu, dd, t + 1);
            int   rc = __shfl_sync(0xffffffffu, rr, t + 2);
            float dcf = __shfl_sync(0xffffffffu, dd, t + 2);
            int   rd = __shfl_sync(0xffffffffu, rr, t + 3);
            float de = __shfl_sync(0xffffffffu, dd, t + 3);
            float xa = g_xw[ra * 32 + j];
            float xb = g_xw[rb * 32 + j];
            float xc = g_xw[rc * 32 + j];
            float xd = g_xw[rd * 32 + j];
            sum += da * xa; sum += db * xb; sum += dcf * xc; sum += de * xd;
        }
        for (; t < cnt; ++t) {
            int   rt = __shfl_sync(0xffffffffu, rr, t);
            float dt = __shfl_sync(0xffffffffu, dd, t);
            sum += dt * g_xw[rt * 32 + j];
        }
    }

    float h = dc * sum + __ldg(b0 + j);

    float uu = wred(h * g_att_a[j]);
    float vv = wred(h * g_att_b[j]);
    float q0 = wred(h * __ldg(W1 + j * 8 + 0));
    float q1 = wred(h * __ldg(W1 + j * 8 + 1));
    float q2 = wred(h * __ldg(W1 + j * 8 + 2));
    float q3 = wred(h * __ldg(W1 + j * 8 + 3));
    float q4 = wred(h * __ldg(W1 + j * 8 + 4));
    float q5 = wred(h * __ldg(W1 + j * 8 + 5));
    float q6 = wred(h * __ldg(W1 + j * 8 + 6));
    float q7 = wred(h * __ldg(W1 + j * 8 + 7));

    if (j == 0) {
        g_u[node] = uu;
        g_v[node] = vv;
        *(float4*)(g_hw + node * 8)     = make_float4(q0, q1, q2, q3);
        *(float4*)(g_hw + node * 8 + 4) = make_float4(q4, q5, q6, q7);
    }
}

// ---------------- 5) attention weights + deg1 -------------------------------
__global__ __launch_bounds__(256) void attn_kernel() {
    int i = blockIdx.x * blockDim.x + threadIdx.x;
    if (i >= N_NODES) return;
    float vc = g_v[i] + g_cst;
    int s = g_off[i], e = g_off[i + 1];
    float sum = 0.f;
    for (int p = s; p < e; ++p) {
        int r = g_src[p];
        float w = fmaxf(g_u[r] + vc, 0.f);              // relu
        float m = ZETA / (1.f + __expf(-w));            // sigmoid * zeta
        m = fminf(m, 1.f);                               // clip (lower clip moot: >0)
        float mw = m * w;
        g_mw[p] = mw;
        sum += mw;
    }
    g_dinv1[i] = rsqrtf(sum + 1.0f);                     // +1 = self loop
}

// ---------------- 6) conv1 --------------------------------------------------
__global__ __launch_bounds__(256) void conv1_kernel(const float* __restrict__ b1,
                                                    float* __restrict__ out) {
    int i = blockIdx.x * blockDim.x + threadIdx.x;
    if (i >= N_NODES) return;
    float d1 = g_dinv1[i];
    float4 a0 = make_float4(0.f, 0.f, 0.f, 0.f);
    float4 a1 = make_float4(0.f, 0.f, 0.f, 0.f);
    int s = g_off[i], e = g_off[i + 1];
    for (int p = s; p < e; ++p) {
        int r = g_src[p];
        float coef = g_dinv1[r] * g_mw[p];
        float4 h0 = *(const float4*)(g_hw + r * 8);
        float4 h1 = *(const float4*)(g_hw + r * 8 + 4);
        a0.x += coef * h0.x; a0.y += coef * h0.y; a0.z += coef * h0.z; a0.w += coef * h0.w;
        a1.x += coef * h1.x; a1.y += coef * h1.y; a1.z += coef * h1.z; a1.w += coef * h1.w;
    }
    float4 s0 = *(const float4*)(g_hw + i * 8);
    float4 s1 = *(const float4*)(g_hw + i * 8 + 4);
    float4 bb0 = *(const float4*)(b1);
    float4 bb1 = *(const float4*)(b1 + 4);
    float4 o0, o1;
    o0.x = d1 * (a0.x + d1 * s0.x) + bb0.x;
    o0.y = d1 * (a0.y + d1 * s0.y) + bb0.y;
    o0.z = d1 * (a0.z + d1 * s0.z) + bb0.z;
    o0.w = d1 * (a0.w + d1 * s0.w) + bb0.w;
    o1.x = d1 * (a1.x + d1 * s1.x) + bb1.x;
    o1.y = d1 * (a1.y + d1 * s1.y) + bb1.y;
    o1.z = d1 * (a1.z + d1 * s1.z) + bb1.z;
    o1.w = d1 * (a1.w + d1 * s1.w) + bb1.w;
    *(float4*)(out + i * 8)     = o0;
    *(float4*)(out + i * 8 + 4) = o1;
}

// ---------------- launch -----------------------------------------------------
extern "C" void kernel_launch(void* const* d_in, const int* in_sizes, int n_in,
                              void* d_out, int out_size) {
    const float* x     = (const float*)d_in[0];
    const int*   eidx  = (const int*)  d_in[1];   // [2, E] int32
    const float* W0    = (const float*)d_in[2];
    const float* b0    = (const float*)d_in[3];
    const float* W1    = (const float*)d_in[4];
    const float* b1    = (const float*)d_in[5];
    const float* Wnb   = (const float*)d_in[6];
    const float* bnb   = (const float*)d_in[7];
    const float* Wself = (const float*)d_in[8];
    const float* bself = (const float*)d_in[9];
    const float* Watt  = (const float*)d_in[10];
    const float* batt  = (const float*)d_in[11];
    float* out = (float*)d_out;

    prep_ab<<<1, 32>>>(Wnb, bnb, Wself, bself, Watt, batt);
    zero_cnt<<<(N_NODES + 255) / 256, 256>>>();
    count_kernel<<<(N_EDGES + 255) / 256, 256>>>(eidx);
    scan1<<<NB_SCAN, 1024>>>();
    scan2<<<1, 32>>>();
    scan3<<<(N_NODES + 255) / 256, 256>>>();
    fill_kernel<<<(N_EDGES + 255) / 256, 256>>>(eidx);
    gemm_xw<<<(N_NODES + 127) / 128, 128>>>(x, W0);
    conv0_kernel<<<(N_NODES * 32 + 255) / 256, 256>>>(b0, W1);
    attn_kernel<<<(N_NODES + 255) / 256, 256>>>();
    conv1_kernel<<<(N_NODES + 255) / 256, 256>>>(b1, out);
}

// round 2
// speedup vs baseline: 1.0167x; 1.0167x over previous
#include <cuda_runtime.h>

// PTDNet-GCN fused pipeline, round 2:
//  - CSR build (count -> scan -> fill)
//  - xw = x @ W0 via f32x2 packed-FFMA SGEMM, then xw *= dinv0 (pre-scaled rows)
//  - conv0: warp-per-node, lane = (edge-subgroup, feature-quad); fused epilogue
//           computes hw = h@W1 and attention scalars u, v via per-warp smem
//  - attn: warp-per-node, lane-per-edge; fused hws = dinv1 * hw
//  - conv1: warp-per-node, 4 edges x 8 features per iter

#define N_NODES 100000
#define N_EDGES 1600000
#define IN_DIM  512
#define H0      32
#define H1      8
#define ZETA    1.01f
#define NB_SCAN 98   // ceil(100000/1024)

// ---------------- scratch (static device memory) ----------------------------
__device__ float g_xw[N_NODES * H0];      // x @ W0, later scaled by dinv0[row]
__device__ float g_hw[N_NODES * H1];      // h @ W1
__device__ float g_hws[N_NODES * H1];     // dinv1[row] * hw
__device__ int   g_cnt[N_NODES];
__device__ int   g_off[N_NODES + 1];
__device__ int   g_cursor[N_NODES];
__device__ int   g_bsum[NB_SCAN];
__device__ int   g_src[N_EDGES];
__device__ float g_mw[N_EDGES];
__device__ float g_dinv0[N_NODES];
__device__ float g_dinv1[N_NODES];
__device__ float g_u[N_NODES];
__device__ float g_v[N_NODES];
__device__ float g_att_a[H0];
__device__ float g_att_b[H0];
__device__ float g_cst;

// ---------------- helpers ---------------------------------------------------
__device__ __forceinline__ float wred(float x) {
    x += __shfl_xor_sync(0xffffffffu, x, 16);
    x += __shfl_xor_sync(0xffffffffu, x, 8);
    x += __shfl_xor_sync(0xffffffffu, x, 4);
    x += __shfl_xor_sync(0xffffffffu, x, 2);
    x += __shfl_xor_sync(0xffffffffu, x, 1);
    return x;
}

// ---------------- attention folding prep -------------------------------------
__global__ void prep_ab(const float* __restrict__ Wnb, const float* __restrict__ bnb,
                        const float* __restrict__ Wself, const float* __restrict__ bself,
                        const float* __restrict__ Watt, const float* __restrict__ batt) {
    int j = threadIdx.x;  // 32 threads
    float a = 0.f, b = 0.f;
#pragma unroll
    for (int q = 0; q < 8; ++q) {
        a += Wnb[j * 8 + q] * Watt[q];
        b += Wself[j * 8 + q] * Watt[8 + q];
    }
    g_att_a[j] = a;
    g_att_b[j] = b;
    if (j == 0) {
        float c = batt[0];
#pragma unroll
        for (int q = 0; q < 8; ++q) c += bnb[q] * Watt[q] + bself[q] * Watt[8 + q];
        g_cst = c;
    }
}

// ---------------- CSR build --------------------------------------------------
__global__ void zero_cnt() {
    int i = blockIdx.x * blockDim.x + threadIdx.x;
    if (i < N_NODES) g_cnt[i] = 0;
}

__global__ void count_kernel(const int* __restrict__ eidx) {
    int e = blockIdx.x * blockDim.x + threadIdx.x;
    if (e >= N_EDGES) return;
    atomicAdd(&g_cnt[eidx[N_EDGES + e]], 1);
}

__global__ __launch_bounds__(1024) void scan1() {
    __shared__ int sm[1024];
    int tid = threadIdx.x;
    int i = blockIdx.x * 1024 + tid;
    int v = (i < N_NODES) ? g_cnt[i] : 0;
    sm[tid] = v;
    __syncthreads();
    for (int o = 1; o < 1024; o <<= 1) {
        int t = (tid >= o) ? sm[tid - o] : 0;
        __syncthreads();
        sm[tid] += t;
        __syncthreads();
    }
    if (i < N_NODES) g_off[i] = sm[tid] - v;
    if (tid == 1023) g_bsum[blockIdx.x] = sm[tid];
}

__global__ void scan2() {
    if (threadIdx.x == 0) {
        int run = 0;
        for (int b = 0; b < NB_SCAN; ++b) {
            int t = g_bsum[b]; g_bsum[b] = run; run += t;
        }
    }
}

__global__ void scan3() {
    int i = blockIdx.x * blockDim.x + threadIdx.x;
    if (i >= N_NODES) return;
    int o = g_off[i] + g_bsum[i >> 10];
    g_off[i] = o;
    g_cursor[i] = o;
    g_dinv0[i] = rsqrtf((float)g_cnt[i] + 1.0f);
    if (i == 0) g_off[N_NODES] = N_EDGES;
}

__global__ void fill_kernel(const int* __restrict__ eidx) {
    int e = blockIdx.x * blockDim.x + threadIdx.x;
    if (e >= N_EDGES) return;
    int r = eidx[e];
    int c = eidx[N_EDGES + e];
    int pos = atomicAdd(&g_cursor[c], 1);
    g_src[pos] = r;
}

// ---------------- xw = x @ W0  (f32x2 packed FFMA SGEMM) ---------------------
__global__ __launch_bounds__(128) void gemm_xw(const float* __restrict__ x,
                                               const float* __restrict__ W0) {
    __shared__ float xs[128 * 33];
    __shared__ float ws[32 * 32];
    int tid = threadIdx.x;
    int row0 = blockIdx.x * 128;
    int r0 = (tid >> 2) * 4;
    int c0 = (tid & 3) * 8;

    unsigned long long acc[4][4];
#pragma unroll
    for (int r = 0; r < 4; ++r)
#pragma unroll
        for (int c = 0; c < 4; ++c) acc[r][c] = 0ull;

    for (int k0 = 0; k0 < IN_DIM; k0 += 32) {
#pragma unroll
        for (int it = 0; it < 8; ++it) {
            int idx = tid + it * 128;
            int rr = idx >> 3;
            int cc = (idx & 7) << 2;
            int grow = row0 + rr;
            float4 v = make_float4(0.f, 0.f, 0.f, 0.f);
            if (grow < N_NODES)
                v = *(const float4*)(x + (size_t)grow * IN_DIM + k0 + cc);
            float* d = xs + rr * 33 + cc;
            d[0] = v.x; d[1] = v.y; d[2] = v.z; d[3] = v.w;
        }
#pragma unroll
        for (int it = 0; it < 2; ++it) {
            int idx = tid + it * 128;
            *(float4*)(ws + idx * 4) = *(const float4*)(W0 + k0 * 32 + idx * 4);
        }
        __syncthreads();

#pragma unroll
        for (int kk = 0; kk < 32; ++kk) {
            unsigned long long xv[4];
#pragma unroll
            for (int r = 0; r < 4; ++r) {
                float xf = xs[(r0 + r) * 33 + kk];
                asm("mov.b64 %0, {%1, %1};" : "=l"(xv[r]) : "f"(xf));
            }
            const unsigned long long* wrow =
                (const unsigned long long*)(ws + kk * 32 + c0);
#pragma unroll
            for (int c = 0; c < 4; ++c) {
                unsigned long long wv = wrow[c];
#pragma unroll
                for (int r = 0; r < 4; ++r)
                    asm("fma.rn.f32x2 %0, %1, %2, %0;"
                        : "+l"(acc[r][c]) : "l"(xv[r]), "l"(wv));
            }
        }
        __syncthreads();
    }

#pragma unroll
    for (int r = 0; r < 4; ++r) {
        int grow = row0 + r0 + r;
        if (grow < N_NODES) {
            unsigned long long* o = (unsigned long long*)(g_xw + grow * 32 + c0);
#pragma unroll
            for (int c = 0; c < 4; ++c) o[c] = acc[r][c];
        }
    }
}

// ---------------- scale xw rows by dinv0 -------------------------------------
__global__ void scale_xw_kernel() {
    int i = blockIdx.x * blockDim.x + threadIdx.x;  // over N*8 float4 slots
    if (i >= N_NODES * 8) return;
    float4 v = ((float4*)g_xw)[i];
    float d = g_dinv0[i >> 3];
    v.x *= d; v.y *= d; v.z *= d; v.w *= d;
    ((float4*)g_xw)[i] = v;
}

// ---------------- conv0 + fused (hw, u, v) -----------------------------------
// Warp per node. lane -> (edge-subgroup g = lane>>3, feature quad f4 = (lane&7)*4).
// 8 edges per loop iteration (2x unroll of 4-edge groups).
__global__ __launch_bounds__(256) void conv0_kernel(const float* __restrict__ b0,
                                                    const float* __restrict__ W1) {
    __shared__ float hsm[8][32];
    int warp = (blockIdx.x * blockDim.x + threadIdx.x) >> 5;
    int lane = threadIdx.x & 31;
    int w = threadIdx.x >> 5;
    if (warp >= N_NODES) return;
    int node = warp;
    int s = g_off[node], e = g_off[node + 1];
    int g = lane >> 3;
    int f4 = (lane & 7) * 4;

    float4 acc;
    if (g == 0) acc = *(const float4*)(g_xw + node * 32 + f4);  // self (pre-scaled)
    else        acc = make_float4(0.f, 0.f, 0.f, 0.f);

    for (int p0 = s; p0 < e; p0 += 8) {
        int pA = p0 + g;
        int pB = p0 + 4 + g;
        int rA = (pA < e) ? g_src[pA] : -1;
        int rB = (pB < e) ? g_src[pB] : -1;
        if (rA >= 0) {
            float4 xv = *(const float4*)(g_xw + rA * 32 + f4);
            acc.x += xv.x; acc.y += xv.y; acc.z += xv.z; acc.w += xv.w;
        }
        if (rB >= 0) {
            float4 xv = *(const float4*)(g_xw + rB * 32 + f4);
            acc.x += xv.x; acc.y += xv.y; acc.z += xv.z; acc.w += xv.w;
        }
    }
    // reduce across the 4 edge-subgroups
    acc.x += __shfl_xor_sync(0xffffffffu, acc.x, 8);
    acc.y += __shfl_xor_sync(0xffffffffu, acc.y, 8);
    acc.z += __shfl_xor_sync(0xffffffffu, acc.z, 8);
    acc.w += __shfl_xor_sync(0xffffffffu, acc.w, 8);
    acc.x += __shfl_xor_sync(0xffffffffu, acc.x, 16);
    acc.y += __shfl_xor_sync(0xffffffffu, acc.y, 16);
    acc.z += __shfl_xor_sync(0xffffffffu, acc.z, 16);
    acc.w += __shfl_xor_sync(0xffffffffu, acc.w, 16);

    float dc = g_dinv0[node];
    if (g == 0) {
        hsm[w][f4 + 0] = dc * acc.x + __ldg(b0 + f4 + 0);
        hsm[w][f4 + 1] = dc * acc.y + __ldg(b0 + f4 + 1);
        hsm[w][f4 + 2] = dc * acc.z + __ldg(b0 + f4 + 2);
        hsm[w][f4 + 3] = dc * acc.w + __ldg(b0 + f4 + 3);
    }
    __syncwarp();

    // epilogue: lanes 0-7 -> hw columns, lane 8 -> u, lane 9 -> v
    float q = 0.f;
    if (lane < 8) {
#pragma unroll
        for (int j = 0; j < 32; ++j) q += hsm[w][j] * __ldg(W1 + j * 8 + lane);
        g_hw[node * 8 + lane] = q;
    } else if (lane == 8) {
#pragma unroll
        for (int j = 0; j < 32; ++j) q += hsm[w][j] * g_att_a[j];
        g_u[node] = q;
    } else if (lane == 9) {
#pragma unroll
        for (int j = 0; j < 32; ++j) q += hsm[w][j] * g_att_b[j];
        g_v[node] = q;
    }
}

// ---------------- attention weights + dinv1 + hws ----------------------------
// Warp per node, lane per edge.
__global__ __launch_bounds__(256) void attn_kernel() {
    int warp = (blockIdx.x * blockDim.x + threadIdx.x) >> 5;
    int lane = threadIdx.x & 31;
    if (warp >= N_NODES) return;
    int node = warp;
    float vc = g_v[node] + g_cst;
    int s = g_off[node], e = g_off[node + 1];
    float sum = 0.f;
    for (int p0 = s; p0 < e; p0 += 32) {
        int p = p0 + lane;
        float mw = 0.f;
        if (p < e) {
            int r = g_src[p];
            float wgt = fmaxf(g_u[r] + vc, 0.f);
            float m = fminf(ZETA / (1.f + __expf(-wgt)), 1.f);
            mw = m * wgt;
            g_mw[p] = mw;
        }
        sum += mw;
    }
    sum = wred(sum);
    float d1 = rsqrtf(sum + 1.0f);   // +1 = self loop weight
    if (lane == 0) g_dinv1[node] = d1;
    if (lane < 8) g_hws[node * 8 + lane] = d1 * g_hw[node * 8 + lane];
}

// ---------------- conv1 ------------------------------------------------------
// Warp per node. lane -> (edge-subgroup g = lane>>3, feature f = lane&7).
__global__ __launch_bounds__(256) void conv1_kernel(const float* __restrict__ b1,
                                                    float* __restrict__ out) {
    int warp = (blockIdx.x * blockDim.x + threadIdx.x) >> 5;
    int lane = threadIdx.x & 31;
    if (warp >= N_NODES) return;
    int node = warp;
    int s = g_off[node], e = g_off[node + 1];
    int g = lane >> 3;
    int f = lane & 7;

    float acc = (g == 0) ? g_hws[node * 8 + f] : 0.f;  // self term

    for (int p0 = s; p0 < e; p0 += 8) {
        int pA = p0 + g;
        int pB = p0 + 4 + g;
        int rA = (pA < e) ? g_src[pA] : -1;
        int rB = (pB < e) ? g_src[pB] : -1;
        float cA = (pA < e) ? g_mw[pA] : 0.f;
        float cB = (pB < e) ? g_mw[pB] : 0.f;
        if (rA >= 0) acc += cA * g_hws[rA * 8 + f];
        if (rB >= 0) acc += cB * g_hws[rB * 8 + f];
    }
    acc += __shfl_xor_sync(0xffffffffu, acc, 8);
    acc += __shfl_xor_sync(0xffffffffu, acc, 16);

    if (lane < 8)
        out[node * 8 + lane] = g_dinv1[node] * acc + __ldg(b1 + lane);
}

// ---------------- launch -----------------------------------------------------
extern "C" void kernel_launch(void* const* d_in, const int* in_sizes, int n_in,
                              void* d_out, int out_size) {
    const float* x     = (const float*)d_in[0];
    const int*   eidx  = (const int*)  d_in[1];
    const float* W0    = (const float*)d_in[2];
    const float* b0    = (const float*)d_in[3];
    const float* W1    = (const float*)d_in[4];
    const float* b1    = (const float*)d_in[5];
    const float* Wnb   = (const float*)d_in[6];
    const float* bnb   = (const float*)d_in[7];
    const float* Wself = (const float*)d_in[8];
    const float* bself = (const float*)d_in[9];
    const float* Watt  = (const float*)d_in[10];
    const float* batt  = (const float*)d_in[11];
    float* out = (float*)d_out;

    prep_ab<<<1, 32>>>(Wnb, bnb, Wself, bself, Watt, batt);
    zero_cnt<<<(N_NODES + 255) / 256, 256>>>();
    count_kernel<<<(N_EDGES + 255) / 256, 256>>>(eidx);
    scan1<<<NB_SCAN, 1024>>>();
    scan2<<<1, 32>>>();
    scan3<<<(N_NODES + 255) / 256, 256>>>();
    fill_kernel<<<(N_EDGES + 255) / 256, 256>>>(eidx);
    gemm_xw<<<(N_NODES + 127) / 128, 128>>>(x, W0);
    scale_xw_kernel<<<(N_NODES * 8 + 255) / 256, 256>>>();
    conv0_kernel<<<(N_NODES * 32 + 255) / 256, 256>>>(b0, W1);
    attn_kernel<<<(N_NODES * 32 + 255) / 256, 256>>>();
    conv1_kernel<<<(N_NODES * 32 + 255) / 256, 256>>>(b1, out);
}

// round 3
// speedup vs baseline: 1.0263x; 1.0094x over previous
#include <cuda_runtime.h>

// PTDNet-GCN fused pipeline, round 3:
//  - zero+prep merged; count; single fused scan (atomic block-base, non-monotone
//    CSR offsets + e = s + cnt); fill
//  - xw = x @ W0 via f32x2 packed-FFMA SGEMM with dinv0 row-scale fused in epilogue
//  - conv0: warp-per-node gather + fused hw/u/v epilogue
//  - attn: warp-per-node -> mw, dinv1, hws
//  - conv1: warp-per-node gather -> out

#define N_NODES 100000
#define N_EDGES 1600000
#define IN_DIM  512
#define H0      32
#define H1      8
#define ZETA    1.01f
#define NB_SCAN 98   // ceil(100000/1024)

// ---------------- scratch (static device memory) ----------------------------
__device__ float g_xw[N_NODES * H0];      // dinv0[row] * (x @ W0)
__device__ float g_hw[N_NODES * H1];      // h @ W1
__device__ float g_hws[N_NODES * H1];     // dinv1[row] * hw
__device__ int   g_cnt[N_NODES];
__device__ int   g_off[N_NODES];          // bucket start (non-monotone partition)
__device__ int   g_cursor[N_NODES];
__device__ int   g_total;
__device__ int   g_src[N_EDGES];
__device__ float g_mw[N_EDGES];
__device__ float g_dinv0[N_NODES];
__device__ float g_dinv1[N_NODES];
__device__ float g_u[N_NODES];
__device__ float g_v[N_NODES];
__device__ float g_att_a[H0];
__device__ float g_att_b[H0];
__device__ float g_cst;

// ---------------- helpers ---------------------------------------------------
__device__ __forceinline__ float wred(float x) {
    x += __shfl_xor_sync(0xffffffffu, x, 16);
    x += __shfl_xor_sync(0xffffffffu, x, 8);
    x += __shfl_xor_sync(0xffffffffu, x, 4);
    x += __shfl_xor_sync(0xffffffffu, x, 2);
    x += __shfl_xor_sync(0xffffffffu, x, 1);
    return x;
}

// ---------------- 1) zero counters + attention folding prep ------------------
__global__ __launch_bounds__(1024) void zero_prep(
        const float* __restrict__ Wnb, const float* __restrict__ bnb,
        const float* __restrict__ Wself, const float* __restrict__ bself,
        const float* __restrict__ Watt, const float* __restrict__ batt) {
    int i = blockIdx.x * 1024 + threadIdx.x;
    if (i < N_NODES) g_cnt[i] = 0;
    if (blockIdx.x == 0) {
        if (threadIdx.x == 0) g_total = 0;
        if (threadIdx.x < 32) {
            int j = threadIdx.x;
            float a = 0.f, b = 0.f;
#pragma unroll
            for (int q = 0; q < 8; ++q) {
                a += Wnb[j * 8 + q] * Watt[q];
                b += Wself[j * 8 + q] * Watt[8 + q];
            }
            g_att_a[j] = a;
            g_att_b[j] = b;
            if (j == 0) {
                float c = batt[0];
#pragma unroll
                for (int q = 0; q < 8; ++q)
                    c += bnb[q] * Watt[q] + bself[q] * Watt[8 + q];
                g_cst = c;
            }
        }
    }
}

// ---------------- 2) in-degree count ----------------------------------------
__global__ void count_kernel(const int* __restrict__ eidx) {
    int e = blockIdx.x * blockDim.x + threadIdx.x;
    if (e >= N_EDGES) return;
    atomicAdd(&g_cnt[eidx[N_EDGES + e]], 1);
}

// ---------------- 3) fused scan: block-local scan + atomic base --------------
__global__ __launch_bounds__(1024) void scan_fused() {
    __shared__ int sm[1024];
    __shared__ int sbase;
    int tid = threadIdx.x;
    int i = blockIdx.x * 1024 + tid;
    int v = (i < N_NODES) ? g_cnt[i] : 0;
    sm[tid] = v;
    __syncthreads();
    for (int o = 1; o < 1024; o <<= 1) {
        int t = (tid >= o) ? sm[tid - o] : 0;
        __syncthreads();
        sm[tid] += t;
        __syncthreads();
    }
    if (tid == 1023) sbase = atomicAdd(&g_total, sm[1023]);
    __syncthreads();
    if (i < N_NODES) {
        int o = sm[tid] - v + sbase;
        g_off[i] = o;
        g_cursor[i] = o;
        g_dinv0[i] = rsqrtf((float)v + 1.0f);
    }
}

// ---------------- 4) CSR fill ------------------------------------------------
__global__ void fill_kernel(const int* __restrict__ eidx) {
    int e = blockIdx.x * blockDim.x + threadIdx.x;
    if (e >= N_EDGES) return;
    int r = eidx[e];
    int c = eidx[N_EDGES + e];
    int pos = atomicAdd(&g_cursor[c], 1);
    g_src[pos] = r;
}

// ---------------- 5) xw = dinv0 * (x @ W0)  (f32x2 packed FFMA) --------------
__global__ __launch_bounds__(128) void gemm_xw(const float* __restrict__ x,
                                               const float* __restrict__ W0) {
    __shared__ float xs[128 * 33];
    __shared__ float ws[32 * 32];
    int tid = threadIdx.x;
    int row0 = blockIdx.x * 128;
    int r0 = (tid >> 2) * 4;
    int c0 = (tid & 3) * 8;

    unsigned long long acc[4][4];
#pragma unroll
    for (int r = 0; r < 4; ++r)
#pragma unroll
        for (int c = 0; c < 4; ++c) acc[r][c] = 0ull;

    for (int k0 = 0; k0 < IN_DIM; k0 += 32) {
#pragma unroll
        for (int it = 0; it < 8; ++it) {
            int idx = tid + it * 128;
            int rr = idx >> 3;
            int cc = (idx & 7) << 2;
            int grow = row0 + rr;
            float4 v = make_float4(0.f, 0.f, 0.f, 0.f);
            if (grow < N_NODES)
                v = *(const float4*)(x + (size_t)grow * IN_DIM + k0 + cc);
            float* d = xs + rr * 33 + cc;
            d[0] = v.x; d[1] = v.y; d[2] = v.z; d[3] = v.w;
        }
#pragma unroll
        for (int it = 0; it < 2; ++it) {
            int idx = tid + it * 128;
            *(float4*)(ws + idx * 4) = *(const float4*)(W0 + k0 * 32 + idx * 4);
        }
        __syncthreads();

#pragma unroll
        for (int kk = 0; kk < 32; ++kk) {
            unsigned long long xv[4];
#pragma unroll
            for (int r = 0; r < 4; ++r) {
                float xf = xs[(r0 + r) * 33 + kk];
                asm("mov.b64 %0, {%1, %1};" : "=l"(xv[r]) : "f"(xf));
            }
            const unsigned long long* wrow =
                (const unsigned long long*)(ws + kk * 32 + c0);
#pragma unroll
            for (int c = 0; c < 4; ++c) {
                unsigned long long wv = wrow[c];
#pragma unroll
                for (int r = 0; r < 4; ++r)
                    asm("fma.rn.f32x2 %0, %1, %2, %0;"
                        : "+l"(acc[r][c]) : "l"(xv[r]), "l"(wv));
            }
        }
        __syncthreads();
    }

#pragma unroll
    for (int r = 0; r < 4; ++r) {
        int grow = row0 + r0 + r;
        if (grow < N_NODES) {
            float d = g_dinv0[grow];
            float2* o = (float2*)(g_xw + grow * 32 + c0);
#pragma unroll
            for (int c = 0; c < 4; ++c) {
                float2 v = *(float2*)&acc[r][c];
                v.x *= d; v.y *= d;
                o[c] = v;
            }
        }
    }
}

// ---------------- 6) conv0 + fused (hw, u, v) --------------------------------
__global__ __launch_bounds__(256) void conv0_kernel(const float* __restrict__ b0,
                                                    const float* __restrict__ W1) {
    __shared__ float hsm[8][32];
    int warp = (blockIdx.x * blockDim.x + threadIdx.x) >> 5;
    int lane = threadIdx.x & 31;
    int w = threadIdx.x >> 5;
    if (warp >= N_NODES) return;
    int node = warp;
    int s = g_off[node];
    int e = s + g_cnt[node];
    int g = lane >> 3;
    int f4 = (lane & 7) * 4;

    float4 acc;
    if (g == 0) acc = *(const float4*)(g_xw + node * 32 + f4);  // self (pre-scaled)
    else        acc = make_float4(0.f, 0.f, 0.f, 0.f);

    for (int p0 = s; p0 < e; p0 += 8) {
        int pA = p0 + g;
        int pB = p0 + 4 + g;
        int rA = (pA < e) ? g_src[pA] : -1;
        int rB = (pB < e) ? g_src[pB] : -1;
        if (rA >= 0) {
            float4 xv = *(const float4*)(g_xw + rA * 32 + f4);
            acc.x += xv.x; acc.y += xv.y; acc.z += xv.z; acc.w += xv.w;
        }
        if (rB >= 0) {
            float4 xv = *(const float4*)(g_xw + rB * 32 + f4);
            acc.x += xv.x; acc.y += xv.y; acc.z += xv.z; acc.w += xv.w;
        }
    }
    acc.x += __shfl_xor_sync(0xffffffffu, acc.x, 8);
    acc.y += __shfl_xor_sync(0xffffffffu, acc.y, 8);
    acc.z += __shfl_xor_sync(0xffffffffu, acc.z, 8);
    acc.w += __shfl_xor_sync(0xffffffffu, acc.w, 8);
    acc.x += __shfl_xor_sync(0xffffffffu, acc.x, 16);
    acc.y += __shfl_xor_sync(0xffffffffu, acc.y, 16);
    acc.z += __shfl_xor_sync(0xffffffffu, acc.z, 16);
    acc.w += __shfl_xor_sync(0xffffffffu, acc.w, 16);

    float dc = g_dinv0[node];
    if (g == 0) {
        hsm[w][f4 + 0] = dc * acc.x + __ldg(b0 + f4 + 0);
        hsm[w][f4 + 1] = dc * acc.y + __ldg(b0 + f4 + 1);
        hsm[w][f4 + 2] = dc * acc.z + __ldg(b0 + f4 + 2);
        hsm[w][f4 + 3] = dc * acc.w + __ldg(b0 + f4 + 3);
    }
    __syncwarp();

    float q = 0.f;
    if (lane < 8) {
#pragma unroll
        for (int j = 0; j < 32; ++j) q += hsm[w][j] * __ldg(W1 + j * 8 + lane);
        g_hw[node * 8 + lane] = q;
    } else if (lane == 8) {
#pragma unroll
        for (int j = 0; j < 32; ++j) q += hsm[w][j] * g_att_a[j];
        g_u[node] = q;
    } else if (lane == 9) {
#pragma unroll
        for (int j = 0; j < 32; ++j) q += hsm[w][j] * g_att_b[j];
        g_v[node] = q;
    }
}

// ---------------- 7) attention weights + dinv1 + hws -------------------------
__global__ __launch_bounds__(256) void attn_kernel() {
    int warp = (blockIdx.x * blockDim.x + threadIdx.x) >> 5;
    int lane = threadIdx.x & 31;
    if (warp >= N_NODES) return;
    int node = warp;
    float vc = g_v[node] + g_cst;
    int s = g_off[node];
    int e = s + g_cnt[node];
    float sum = 0.f;
    for (int p0 = s; p0 < e; p0 += 32) {
        int p = p0 + lane;
        float mw = 0.f;
        if (p < e) {
            int r = g_src[p];
            float wgt = fmaxf(g_u[r] + vc, 0.f);
            float m = fminf(ZETA / (1.f + __expf(-wgt)), 1.f);
            mw = m * wgt;
            g_mw[p] = mw;
        }
        sum += mw;
    }
    sum = wred(sum);
    float d1 = rsqrtf(sum + 1.0f);
    if (lane == 0) g_dinv1[node] = d1;
    if (lane < 8) g_hws[node * 8 + lane] = d1 * g_hw[node * 8 + lane];
}

// ---------------- 8) conv1 ---------------------------------------------------
__global__ __launch_bounds__(256) void conv1_kernel(const float* __restrict__ b1,
                                                    float* __restrict__ out) {
    int warp = (blockIdx.x * blockDim.x + threadIdx.x) >> 5;
    int lane = threadIdx.x & 31;
    if (warp >= N_NODES) return;
    int node = warp;
    int s = g_off[node];
    int e = s + g_cnt[node];
    int g = lane >> 3;
    int f = lane & 7;

    float acc = (g == 0) ? g_hws[node * 8 + f] : 0.f;  // self term

    for (int p0 = s; p0 < e; p0 += 8) {
        int pA = p0 + g;
        int pB = p0 + 4 + g;
        int rA = (pA < e) ? g_src[pA] : -1;
        int rB = (pB < e) ? g_src[pB] : -1;
        float cA = (pA < e) ? g_mw[pA] : 0.f;
        float cB = (pB < e) ? g_mw[pB] : 0.f;
        if (rA >= 0) acc += cA * g_hws[rA * 8 + f];
        if (rB >= 0) acc += cB * g_hws[rB * 8 + f];
    }
    acc += __shfl_xor_sync(0xffffffffu, acc, 8);
    acc += __shfl_xor_sync(0xffffffffu, acc, 16);

    if (lane < 8)
        out[node * 8 + lane] = g_dinv1[node] * acc + __ldg(b1 + lane);
}

// ---------------- launch -----------------------------------------------------
extern "C" void kernel_launch(void* const* d_in, const int* in_sizes, int n_in,
                              void* d_out, int out_size) {
    const float* x     = (const float*)d_in[0];
    const int*   eidx  = (const int*)  d_in[1];
    const float* W0    = (const float*)d_in[2];
    const float* b0    = (const float*)d_in[3];
    const float* W1    = (const float*)d_in[4];
    const float* b1    = (const float*)d_in[5];
    const float* Wnb   = (const float*)d_in[6];
    const float* bnb   = (const float*)d_in[7];
    const float* Wself = (const float*)d_in[8];
    const float* bself = (const float*)d_in[9];
    const float* Watt  = (const float*)d_in[10];
    const float* batt  = (const float*)d_in[11];
    float* out = (float*)d_out;

    zero_prep<<<NB_SCAN, 1024>>>(Wnb, bnb, Wself, bself, Watt, batt);
    count_kernel<<<(N_EDGES + 255) / 256, 256>>>(eidx);
    scan_fused<<<NB_SCAN, 1024>>>();
    fill_kernel<<<(N_EDGES + 255) / 256, 256>>>(eidx);
    gemm_xw<<<(N_NODES + 127) / 128, 128>>>(x, W0);
    conv0_kernel<<<(N_NODES * 32 + 255) / 256, 256>>>(b0, W1);
    attn_kernel<<<(N_NODES * 32 + 255) / 256, 256>>>();
    conv1_kernel<<<(N_NODES * 32 + 255) / 256, 256>>>(b1, out);
}

// round 4
// speedup vs baseline: 1.0922x; 1.0642x over previous
#include <cuda_runtime.h>

// PTDNet-GCN fused pipeline, round 4:
//  - zero+prep; count (int4 x4); fused scan; gemm (moved to launch idx 3 for ncu);
//    fill (2 edges/thread, MLP-batched); conv0; attn; conv1
//  - gemm: 256 threads/block, 256 rows/block, f32x2 packed FFMA, dinv0 fused
//    (computed from g_cnt, so gemm only depends on count)

#define N_NODES 100000
#define N_EDGES 1600000
#define IN_DIM  512
#define H0      32
#define H1      8
#define ZETA    1.01f
#define NB_SCAN 98   // ceil(100000/1024)

// ---------------- scratch (static device memory) ----------------------------
__device__ float g_xw[N_NODES * H0];      // dinv0[row] * (x @ W0)
__device__ float g_hw[N_NODES * H1];      // h @ W1
__device__ float g_hws[N_NODES * H1];     // dinv1[row] * hw
__device__ int   g_cnt[N_NODES];
__device__ int   g_off[N_NODES];          // bucket start (non-monotone partition)
__device__ int   g_cursor[N_NODES];
__device__ int   g_total;
__device__ int   g_src[N_EDGES];
__device__ float g_mw[N_EDGES];
__device__ float g_dinv0[N_NODES];
__device__ float g_dinv1[N_NODES];
__device__ float g_u[N_NODES];
__device__ float g_v[N_NODES];
__device__ float g_att_a[H0];
__device__ float g_att_b[H0];
__device__ float g_cst;

// ---------------- helpers ---------------------------------------------------
__device__ __forceinline__ float wred(float x) {
    x += __shfl_xor_sync(0xffffffffu, x, 16);
    x += __shfl_xor_sync(0xffffffffu, x, 8);
    x += __shfl_xor_sync(0xffffffffu, x, 4);
    x += __shfl_xor_sync(0xffffffffu, x, 2);
    x += __shfl_xor_sync(0xffffffffu, x, 1);
    return x;
}

// ---------------- 1) zero counters + attention folding prep ------------------
__global__ __launch_bounds__(1024) void zero_prep(
        const float* __restrict__ Wnb, const float* __restrict__ bnb,
        const float* __restrict__ Wself, const float* __restrict__ bself,
        const float* __restrict__ Watt, const float* __restrict__ batt) {
    int i = blockIdx.x * 1024 + threadIdx.x;
    if (i < N_NODES) g_cnt[i] = 0;
    if (blockIdx.x == 0) {
        if (threadIdx.x == 0) g_total = 0;
        if (threadIdx.x < 32) {
            int j = threadIdx.x;
            float a = 0.f, b = 0.f;
#pragma unroll
            for (int q = 0; q < 8; ++q) {
                a += Wnb[j * 8 + q] * Watt[q];
                b += Wself[j * 8 + q] * Watt[8 + q];
            }
            g_att_a[j] = a;
            g_att_b[j] = b;
            if (j == 0) {
                float c = batt[0];
#pragma unroll
                for (int q = 0; q < 8; ++q)
                    c += bnb[q] * Watt[q] + bself[q] * Watt[8 + q];
                g_cst = c;
            }
        }
    }
}

// ---------------- 2) in-degree count (4 edges / thread, int4) ----------------
__global__ void count_kernel(const int* __restrict__ eidx) {
    int t = blockIdx.x * blockDim.x + threadIdx.x;
    if (t >= N_EDGES / 4) return;
    int4 c = *(const int4*)(eidx + N_EDGES + t * 4);
    atomicAdd(&g_cnt[c.x], 1);
    atomicAdd(&g_cnt[c.y], 1);
    atomicAdd(&g_cnt[c.z], 1);
    atomicAdd(&g_cnt[c.w], 1);
}

// ---------------- 3) fused scan: block-local scan + atomic base --------------
__global__ __launch_bounds__(1024) void scan_fused() {
    __shared__ int sm[1024];
    __shared__ int sbase;
    int tid = threadIdx.x;
    int i = blockIdx.x * 1024 + tid;
    int v = (i < N_NODES) ? g_cnt[i] : 0;
    sm[tid] = v;
    __syncthreads();
    for (int o = 1; o < 1024; o <<= 1) {
        int t = (tid >= o) ? sm[tid - o] : 0;
        __syncthreads();
        sm[tid] += t;
        __syncthreads();
    }
    if (tid == 1023) sbase = atomicAdd(&g_total, sm[1023]);
    __syncthreads();
    if (i < N_NODES) {
        int o = sm[tid] - v + sbase;
        g_off[i] = o;
        g_cursor[i] = o;
        g_dinv0[i] = rsqrtf((float)v + 1.0f);
    }
}

// ---------------- 4) xw = dinv0 * (x @ W0)  (f32x2 packed FFMA) --------------
// 256 threads/block, 256 rows x 32 cols per block; thread = 4 rows x 8 cols.
__global__ __launch_bounds__(256) void gemm_xw(const float* __restrict__ x,
                                               const float* __restrict__ W0) {
    __shared__ float xs[256 * 33];
    __shared__ float ws[32 * 32];
    int tid = threadIdx.x;
    int row0 = blockIdx.x * 256;
    int r0 = (tid >> 2) * 4;         // 0..252
    int c0 = (tid & 3) * 8;          // 0,8,16,24

    unsigned long long acc[4][4];
#pragma unroll
    for (int r = 0; r < 4; ++r)
#pragma unroll
        for (int c = 0; c < 4; ++c) acc[r][c] = 0ull;

    for (int k0 = 0; k0 < IN_DIM; k0 += 32) {
#pragma unroll
        for (int it = 0; it < 8; ++it) {
            int idx = tid + it * 256;        // 0..2047 float4 slots
            int rr = idx >> 3;
            int cc = (idx & 7) << 2;
            int grow = row0 + rr;
            float4 v = make_float4(0.f, 0.f, 0.f, 0.f);
            if (grow < N_NODES)
                v = *(const float4*)(x + (size_t)grow * IN_DIM + k0 + cc);
            float* d = xs + rr * 33 + cc;
            d[0] = v.x; d[1] = v.y; d[2] = v.z; d[3] = v.w;
        }
        if (tid < 256) {
            *(float4*)(ws + tid * 4) = *(const float4*)(W0 + k0 * 32 + tid * 4);
        }
        __syncthreads();

#pragma unroll
        for (int kk = 0; kk < 32; ++kk) {
            unsigned long long xv[4];
#pragma unroll
            for (int r = 0; r < 4; ++r) {
                float xf = xs[(r0 + r) * 33 + kk];
                asm("mov.b64 %0, {%1, %1};" : "=l"(xv[r]) : "f"(xf));
            }
            // 8 cols of W as two float4 (LDS.128)
            float4 wq0 = *(const float4*)(ws + kk * 32 + c0);
            float4 wq1 = *(const float4*)(ws + kk * 32 + c0 + 4);
            unsigned long long wv[4];
            wv[0] = *(unsigned long long*)&wq0.x;
            wv[1] = *(unsigned long long*)&wq0.z;
            wv[2] = *(unsigned long long*)&wq1.x;
            wv[3] = *(unsigned long long*)&wq1.z;
#pragma unroll
            for (int c = 0; c < 4; ++c) {
#pragma unroll
                for (int r = 0; r < 4; ++r)
                    asm("fma.rn.f32x2 %0, %1, %2, %0;"
                        : "+l"(acc[r][c]) : "l"(xv[r]), "l"(wv[c]));
            }
        }
        __syncthreads();
    }

#pragma unroll
    for (int r = 0; r < 4; ++r) {
        int grow = row0 + r0 + r;
        if (grow < N_NODES) {
            float d = rsqrtf((float)g_cnt[grow] + 1.0f);
            float2* o = (float2*)(g_xw + grow * 32 + c0);
#pragma unroll
            for (int c = 0; c < 4; ++c) {
                float2 v = *(float2*)&acc[r][c];
                v.x *= d; v.y *= d;
                o[c] = v;
            }
        }
    }
}

// ---------------- 5) CSR fill (2 edges / thread, batched loads) --------------
__global__ void fill_kernel(const int* __restrict__ eidx) {
    int t = blockIdx.x * blockDim.x + threadIdx.x;
    if (t >= N_EDGES / 2) return;
    int2 r = *(const int2*)(eidx + t * 2);
    int2 c = *(const int2*)(eidx + N_EDGES + t * 2);
    int pos0 = atomicAdd(&g_cursor[c.x], 1);
    int pos1 = atomicAdd(&g_cursor[c.y], 1);
    g_src[pos0] = r.x;
    g_src[pos1] = r.y;
}

// ---------------- 6) conv0 + fused (hw, u, v) --------------------------------
__global__ __launch_bounds__(256) void conv0_kernel(const float* __restrict__ b0,
                                                    const float* __restrict__ W1) {
    __shared__ float hsm[8][32];
    int warp = (blockIdx.x * blockDim.x + threadIdx.x) >> 5;
    int lane = threadIdx.x & 31;
    int w = threadIdx.x >> 5;
    if (warp >= N_NODES) return;
    int node = warp;
    int s = g_off[node];
    int e = s + g_cnt[node];
    int g = lane >> 3;
    int f4 = (lane & 7) * 4;

    float4 acc;
    if (g == 0) acc = *(const float4*)(g_xw + node * 32 + f4);  // self (pre-scaled)
    else        acc = make_float4(0.f, 0.f, 0.f, 0.f);

    for (int p0 = s; p0 < e; p0 += 8) {
        int pA = p0 + g;
        int pB = p0 + 4 + g;
        int rA = (pA < e) ? g_src[pA] : -1;
        int rB = (pB < e) ? g_src[pB] : -1;
        if (rA >= 0) {
            float4 xv = *(const float4*)(g_xw + rA * 32 + f4);
            acc.x += xv.x; acc.y += xv.y; acc.z += xv.z; acc.w += xv.w;
        }
        if (rB >= 0) {
            float4 xv = *(const float4*)(g_xw + rB * 32 + f4);
            acc.x += xv.x; acc.y += xv.y; acc.z += xv.z; acc.w += xv.w;
        }
    }
    acc.x += __shfl_xor_sync(0xffffffffu, acc.x, 8);
    acc.y += __shfl_xor_sync(0xffffffffu, acc.y, 8);
    acc.z += __shfl_xor_sync(0xffffffffu, acc.z, 8);
    acc.w += __shfl_xor_sync(0xffffffffu, acc.w, 8);
    acc.x += __shfl_xor_sync(0xffffffffu, acc.x, 16);
    acc.y += __shfl_xor_sync(0xffffffffu, acc.y, 16);
    acc.z += __shfl_xor_sync(0xffffffffu, acc.z, 16);
    acc.w += __shfl_xor_sync(0xffffffffu, acc.w, 16);

    float dc = g_dinv0[node];
    if (g == 0) {
        hsm[w][f4 + 0] = dc * acc.x + __ldg(b0 + f4 + 0);
        hsm[w][f4 + 1] = dc * acc.y + __ldg(b0 + f4 + 1);
        hsm[w][f4 + 2] = dc * acc.z + __ldg(b0 + f4 + 2);
        hsm[w][f4 + 3] = dc * acc.w + __ldg(b0 + f4 + 3);
    }
    __syncwarp();

    float q = 0.f;
    if (lane < 8) {
#pragma unroll
        for (int j = 0; j < 32; ++j) q += hsm[w][j] * __ldg(W1 + j * 8 + lane);
        g_hw[node * 8 + lane] = q;
    } else if (lane == 8) {
#pragma unroll
        for (int j = 0; j < 32; ++j) q += hsm[w][j] * g_att_a[j];
        g_u[node] = q;
    } else if (lane == 9) {
#pragma unroll
        for (int j = 0; j < 32; ++j) q += hsm[w][j] * g_att_b[j];
        g_v[node] = q;
    }
}

// ---------------- 7) attention weights + dinv1 + hws -------------------------
__global__ __launch_bounds__(256) void attn_kernel() {
    int warp = (blockIdx.x * blockDim.x + threadIdx.x) >> 5;
    int lane = threadIdx.x & 31;
    if (warp >= N_NODES) return;
    int node = warp;
    float vc = g_v[node] + g_cst;
    int s = g_off[node];
    int e = s + g_cnt[node];
    float sum = 0.f;
    for (int p0 = s; p0 < e; p0 += 32) {
        int p = p0 + lane;
        float mw = 0.f;
        if (p < e) {
            int r = g_src[p];
            float wgt = fmaxf(g_u[r] + vc, 0.f);
            float m = fminf(ZETA / (1.f + __expf(-wgt)), 1.f);
            mw = m * wgt;
            g_mw[p] = mw;
        }
        sum += mw;
    }
    sum = wred(sum);
    float d1 = rsqrtf(sum + 1.0f);
    if (lane == 0) g_dinv1[node] = d1;
    if (lane < 8) g_hws[node * 8 + lane] = d1 * g_hw[node * 8 + lane];
}

// ---------------- 8) conv1 ---------------------------------------------------
__global__ __launch_bounds__(256) void conv1_kernel(const float* __restrict__ b1,
                                                    float* __restrict__ out) {
    int warp = (blockIdx.x * blockDim.x + threadIdx.x) >> 5;
    int lane = threadIdx.x & 31;
    if (warp >= N_NODES) return;
    int node = warp;
    int s = g_off[node];
    int e = s + g_cnt[node];
    int g = lane >> 3;
    int f = lane & 7;

    float acc = (g == 0) ? g_hws[node * 8 + f] : 0.f;  // self term

    for (int p0 = s; p0 < e; p0 += 8) {
        int pA = p0 + g;
        int pB = p0 + 4 + g;
        int rA = (pA < e) ? g_src[pA] : -1;
        int rB = (pB < e) ? g_src[pB] : -1;
        float cA = (pA < e) ? g_mw[pA] : 0.f;
        float cB = (pB < e) ? g_mw[pB] : 0.f;
        if (rA >= 0) acc += cA * g_hws[rA * 8 + f];
        if (rB >= 0) acc += cB * g_hws[rB * 8 + f];
    }
    acc += __shfl_xor_sync(0xffffffffu, acc, 8);
    acc += __shfl_xor_sync(0xffffffffu, acc, 16);

    if (lane < 8)
        out[node * 8 + lane] = g_dinv1[node] * acc + __ldg(b1 + lane);
}

// ---------------- launch -----------------------------------------------------
extern "C" void kernel_launch(void* const* d_in, const int* in_sizes, int n_in,
                              void* d_out, int out_size) {
    const float* x     = (const float*)d_in[0];
    const int*   eidx  = (const int*)  d_in[1];
    const float* W0    = (const float*)d_in[2];
    const float* b0    = (const float*)d_in[3];
    const float* W1    = (const float*)d_in[4];
    const float* b1    = (const float*)d_in[5];
    const float* Wnb   = (const float*)d_in[6];
    const float* bnb   = (const float*)d_in[7];
    const float* Wself = (const float*)d_in[8];
    const float* bself = (const float*)d_in[9];
    const float* Watt  = (const float*)d_in[10];
    const float* batt  = (const float*)d_in[11];
    float* out = (float*)d_out;

    zero_prep<<<NB_SCAN, 1024>>>(Wnb, bnb, Wself, bself, Watt, batt);         // 0
    count_kernel<<<(N_EDGES / 4 + 255) / 256, 256>>>(eidx);                   // 1
    scan_fused<<<NB_SCAN, 1024>>>();                                          // 2
    gemm_xw<<<(N_NODES + 255) / 256, 256>>>(x, W0);                           // 3 (profiled)
    fill_kernel<<<(N_EDGES / 2 + 255) / 256, 256>>>(eidx);                    // 4
    conv0_kernel<<<(N_NODES * 32 + 255) / 256, 256>>>(b0, W1);                // 5
    attn_kernel<<<(N_NODES * 32 + 255) / 256, 256>>>();                       // 6
    conv1_kernel<<<(N_NODES * 32 + 255) / 256, 256>>>(b1, out);               // 7
}

// round 6
// speedup vs baseline: 1.1282x; 1.0330x over previous
#include <cuda_runtime.h>

// PTDNet-GCN fused pipeline, round 5:
//  - GEMM rebuilt on tensor cores: tf32 mma.sync m16n8k8 with 3xTF32 (hi/lo)
//    error compensation; warp-per-32-rows, zero smem, A-frags via direct __ldg,
//    W pre-swizzled into fragment order (done inside zero_prep).
//  - Everything else as round 4.

#define N_NODES 100000
#define N_EDGES 1600000
#define IN_DIM  512
#define H0      32
#define H1      8
#define ZETA    1.01f
#define NB_SCAN 98   // ceil(100000/1024)
#define N_WARPS_GEMM 3125   // 100000 / 32

// ---------------- scratch (static device memory) ----------------------------
__device__ float  g_xw[N_NODES * H0];     // dinv0[row] * (x @ W0)
__device__ float  g_hw[N_NODES * H1];     // h @ W1
__device__ float  g_hws[N_NODES * H1];    // dinv1[row] * hw
__device__ int    g_cnt[N_NODES];
__device__ int    g_off[N_NODES];         // bucket start (non-monotone partition)
__device__ int    g_cursor[N_NODES];
__device__ int    g_total;
__device__ int    g_src[N_EDGES];
__device__ float  g_mw[N_EDGES];
__device__ float  g_dinv0[N_NODES];
__device__ float  g_dinv1[N_NODES];
__device__ float  g_u[N_NODES];
__device__ float  g_v[N_NODES];
__device__ float  g_att_a[H0];
__device__ float  g_att_b[H0];
__device__ float  g_cst;
// W0 fragments: [64 k-steps][4 n-tiles][32 lanes] -> (b0_hi, b1_hi, b0_lo, b1_lo)
__device__ float4 g_wf[64 * 4 * 32];

// ---------------- helpers ---------------------------------------------------
__device__ __forceinline__ float wred(float x) {
    x += __shfl_xor_sync(0xffffffffu, x, 16);
    x += __shfl_xor_sync(0xffffffffu, x, 8);
    x += __shfl_xor_sync(0xffffffffu, x, 4);
    x += __shfl_xor_sync(0xffffffffu, x, 2);
    x += __shfl_xor_sync(0xffffffffu, x, 1);
    return x;
}

__device__ __forceinline__ unsigned f2tf(float x) {
    unsigned u;
    asm("cvt.rna.tf32.f32 %0, %1;" : "=r"(u) : "f"(x));
    return u;
}

__device__ __forceinline__ void mma_tf32(float* d, const unsigned* a,
                                         unsigned b0, unsigned b1) {
    asm("mma.sync.aligned.m16n8k8.row.col.f32.tf32.tf32.f32 "
        "{%0,%1,%2,%3}, {%4,%5,%6,%7}, {%8,%9}, {%0,%1,%2,%3};"
        : "+f"(d[0]), "+f"(d[1]), "+f"(d[2]), "+f"(d[3])
        : "r"(a[0]), "r"(a[1]), "r"(a[2]), "r"(a[3]), "r"(b0), "r"(b1));
}

// ---------------- 1) zero counters + attn prep + W fragment swizzle ----------
__global__ __launch_bounds__(1024) void zero_prep(
        const float* __restrict__ W0,
        const float* __restrict__ Wnb, const float* __restrict__ bnb,
        const float* __restrict__ Wself, const float* __restrict__ bself,
        const float* __restrict__ Watt, const float* __restrict__ batt) {
    int i = blockIdx.x * 1024 + threadIdx.x;
    if (i < N_NODES) g_cnt[i] = 0;
    if (blockIdx.x == 0) {
        if (threadIdx.x == 0) g_total = 0;
        if (threadIdx.x < 32) {
            int j = threadIdx.x;
            float a = 0.f, b = 0.f;
#pragma unroll
            for (int q = 0; q < 8; ++q) {
                a += Wnb[j * 8 + q] * Watt[q];
                b += Wself[j * 8 + q] * Watt[8 + q];
            }
            g_att_a[j] = a;
            g_att_b[j] = b;
            if (j == 0) {
                float c = batt[0];
#pragma unroll
                for (int q = 0; q < 8; ++q)
                    c += bnb[q] * Watt[q] + bself[q] * Watt[8 + q];
                g_cst = c;
            }
        }
    } else if (blockIdx.x <= 8) {
        // W fragment swizzle: idx over 64*4*32 = 8192 entries
        int idx = (blockIdx.x - 1) * 1024 + threadIdx.x;
        int s = idx >> 7;            // k-step
        int t = (idx >> 5) & 3;      // n-tile
        int lane = idx & 31;
        int tig = lane & 3, gid = lane >> 2;
        float b0 = W0[(8 * s + tig) * 32 + 8 * t + gid];
        float b1 = W0[(8 * s + tig + 4) * 32 + 8 * t + gid];
        unsigned b0h = f2tf(b0), b1h = f2tf(b1);
        float b0hf = __uint_as_float(b0h), b1hf = __uint_as_float(b1h);
        unsigned b0l = f2tf(b0 - b0hf), b1l = f2tf(b1 - b1hf);
        g_wf[idx] = make_float4(b0hf, b1hf,
                                __uint_as_float(b0l), __uint_as_float(b1l));
    }
}

// ---------------- 2) in-degree count (4 edges / thread, int4) ----------------
__global__ void count_kernel(const int* __restrict__ eidx) {
    int t = blockIdx.x * blockDim.x + threadIdx.x;
    if (t >= N_EDGES / 4) return;
    int4 c = *(const int4*)(eidx + N_EDGES + t * 4);
    atomicAdd(&g_cnt[c.x], 1);
    atomicAdd(&g_cnt[c.y], 1);
    atomicAdd(&g_cnt[c.z], 1);
    atomicAdd(&g_cnt[c.w], 1);
}

// ---------------- 3) fused scan: block-local scan + atomic base --------------
__global__ __launch_bounds__(1024) void scan_fused() {
    __shared__ int sm[1024];
    __shared__ int sbase;
    int tid = threadIdx.x;
    int i = blockIdx.x * 1024 + tid;
    int v = (i < N_NODES) ? g_cnt[i] : 0;
    sm[tid] = v;
    __syncthreads();
    for (int o = 1; o < 1024; o <<= 1) {
        int t = (tid >= o) ? sm[tid - o] : 0;
        __syncthreads();
        sm[tid] += t;
        __syncthreads();
    }
    if (tid == 1023) sbase = atomicAdd(&g_total, sm[1023]);
    __syncthreads();
    if (i < N_NODES) {
        int o = sm[tid] - v + sbase;
        g_off[i] = o;
        g_cursor[i] = o;
        g_dinv0[i] = rsqrtf((float)v + 1.0f);
    }
}

// ---------------- 4) xw = dinv0 * (x @ W0)  (tf32 mma, 3xTF32) ---------------
// Warp per 32 rows; 2 m-tiles x 4 n-tiles of m16n8k8; A frags via direct ldg.
__global__ __launch_bounds__(256) void gemm_xw(const float* __restrict__ x) {
    int wid = (blockIdx.x * blockDim.x + threadIdx.x) >> 5;
    if (wid >= N_WARPS_GEMM) return;
    int lane = threadIdx.x & 31;
    int gid = lane >> 2, tig = lane & 3;
    int row0 = wid * 32;

    const float* p0 = x + (size_t)(row0 + gid) * IN_DIM;
    const float* p1 = x + (size_t)(row0 + gid + 8) * IN_DIM;
    const float* p2 = x + (size_t)(row0 + gid + 16) * IN_DIM;
    const float* p3 = x + (size_t)(row0 + gid + 24) * IN_DIM;

    float acc[2][4][4];
#pragma unroll
    for (int m = 0; m < 2; ++m)
#pragma unroll
        for (int t = 0; t < 4; ++t)
#pragma unroll
            for (int r = 0; r < 4; ++r) acc[m][t][r] = 0.f;

#pragma unroll 2
    for (int s = 0; s < 64; ++s) {
        int k0 = s * 8 + tig;
        float a[2][4];
        a[0][0] = __ldg(p0 + k0);     a[0][1] = __ldg(p1 + k0);
        a[0][2] = __ldg(p0 + k0 + 4); a[0][3] = __ldg(p1 + k0 + 4);
        a[1][0] = __ldg(p2 + k0);     a[1][1] = __ldg(p3 + k0);
        a[1][2] = __ldg(p2 + k0 + 4); a[1][3] = __ldg(p3 + k0 + 4);

        unsigned ah[2][4], al[2][4];
#pragma unroll
        for (int m = 0; m < 2; ++m)
#pragma unroll
            for (int j = 0; j < 4; ++j) {
                unsigned h = f2tf(a[m][j]);
                ah[m][j] = h;
                al[m][j] = f2tf(a[m][j] - __uint_as_float(h));
            }

#pragma unroll
        for (int t = 0; t < 4; ++t) {
            float4 w = __ldg(&g_wf[(s * 4 + t) * 32 + lane]);
            unsigned bh0 = __float_as_uint(w.x), bh1 = __float_as_uint(w.y);
            unsigned bl0 = __float_as_uint(w.z), bl1 = __float_as_uint(w.w);
#pragma unroll
            for (int m = 0; m < 2; ++m) {
                mma_tf32(acc[m][t], ah[m], bh0, bh1);
                mma_tf32(acc[m][t], al[m], bh0, bh1);
                mma_tf32(acc[m][t], ah[m], bl0, bl1);
            }
        }
    }

    // epilogue: scale rows by rsqrt(indeg+1), store float2 (c0,c1)/(c2,c3)
#pragma unroll
    for (int m = 0; m < 2; ++m) {
        int rA = row0 + m * 16 + gid;
        int rB = rA + 8;
        float dA = rsqrtf((float)g_cnt[rA] + 1.f);
        float dB = rsqrtf((float)g_cnt[rB] + 1.f);
#pragma unroll
        for (int t = 0; t < 4; ++t) {
            int col = t * 8 + tig * 2;
            *(float2*)(g_xw + rA * 32 + col) =
                make_float2(acc[m][t][0] * dA, acc[m][t][1] * dA);
            *(float2*)(g_xw + rB * 32 + col) =
                make_float2(acc[m][t][2] * dB, acc[m][t][3] * dB);
        }
    }
}

// ---------------- 5) CSR fill (2 edges / thread, batched loads) --------------
__global__ void fill_kernel(const int* __restrict__ eidx) {
    int t = blockIdx.x * blockDim.x + threadIdx.x;
    if (t >= N_EDGES / 2) return;
    int2 r = *(const int2*)(eidx + t * 2);
    int2 c = *(const int2*)(eidx + N_EDGES + t * 2);
    int pos0 = atomicAdd(&g_cursor[c.x], 1);
    int pos1 = atomicAdd(&g_cursor[c.y], 1);
    g_src[pos0] = r.x;
    g_src[pos1] = r.y;
}

// ---------------- 6) conv0 + fused (hw, u, v) --------------------------------
__global__ __launch_bounds__(256) void conv0_kernel(const float* __restrict__ b0,
                                                    const float* __restrict__ W1) {
    __shared__ float hsm[8][32];
    int warp = (blockIdx.x * blockDim.x + threadIdx.x) >> 5;
    int lane = threadIdx.x & 31;
    int w = threadIdx.x >> 5;
    if (warp >= N_NODES) return;
    int node = warp;
    int s = g_off[node];
    int e = s + g_cnt[node];
    int g = lane >> 3;
    int f4 = (lane & 7) * 4;

    float4 acc;
    if (g == 0) acc = *(const float4*)(g_xw + node * 32 + f4);  // self (pre-scaled)
    else        acc = make_float4(0.f, 0.f, 0.f, 0.f);

    for (int p0 = s; p0 < e; p0 += 8) {
        int pA = p0 + g;
        int pB = p0 + 4 + g;
        int rA = (pA < e) ? g_src[pA] : -1;
        int rB = (pB < e) ? g_src[pB] : -1;
        if (rA >= 0) {
            float4 xv = *(const float4*)(g_xw + rA * 32 + f4);
            acc.x += xv.x; acc.y += xv.y; acc.z += xv.z; acc.w += xv.w;
        }
        if (rB >= 0) {
            float4 xv = *(const float4*)(g_xw + rB * 32 + f4);
            acc.x += xv.x; acc.y += xv.y; acc.z += xv.z; acc.w += xv.w;
        }
    }
    acc.x += __shfl_xor_sync(0xffffffffu, acc.x, 8);
    acc.y += __shfl_xor_sync(0xffffffffu, acc.y, 8);
    acc.z += __shfl_xor_sync(0xffffffffu, acc.z, 8);
    acc.w += __shfl_xor_sync(0xffffffffu, acc.w, 8);
    acc.x += __shfl_xor_sync(0xffffffffu, acc.x, 16);
    acc.y += __shfl_xor_sync(0xffffffffu, acc.y, 16);
    acc.z += __shfl_xor_sync(0xffffffffu, acc.z, 16);
    acc.w += __shfl_xor_sync(0xffffffffu, acc.w, 16);

    float dc = g_dinv0[node];
    if (g == 0) {
        hsm[w][f4 + 0] = dc * acc.x + __ldg(b0 + f4 + 0);
        hsm[w][f4 + 1] = dc * acc.y + __ldg(b0 + f4 + 1);
        hsm[w][f4 + 2] = dc * acc.z + __ldg(b0 + f4 + 2);
        hsm[w][f4 + 3] = dc * acc.w + __ldg(b0 + f4 + 3);
    }
    __syncwarp();

    float q = 0.f;
    if (lane < 8) {
#pragma unroll
        for (int j = 0; j < 32; ++j) q += hsm[w][j] * __ldg(W1 + j * 8 + lane);
        g_hw[node * 8 + lane] = q;
    } else if (lane == 8) {
#pragma unroll
        for (int j = 0; j < 32; ++j) q += hsm[w][j] * g_att_a[j];
        g_u[node] = q;
    } else if (lane == 9) {
#pragma unroll
        for (int j = 0; j < 32; ++j) q += hsm[w][j] * g_att_b[j];
        g_v[node] = q;
    }
}

// ---------------- 7) attention weights + dinv1 + hws -------------------------
__global__ __launch_bounds__(256) void attn_kernel() {
    int warp = (blockIdx.x * blockDim.x + threadIdx.x) >> 5;
    int lane = threadIdx.x & 31;
    if (warp >= N_NODES) return;
    int node = warp;
    float vc = g_v[node] + g_cst;
    int s = g_off[node];
    int e = s + g_cnt[node];
    float sum = 0.f;
    for (int p0 = s; p0 < e; p0 += 32) {
        int p = p0 + lane;
        float mw = 0.f;
        if (p < e) {
            int r = g_src[p];
            float wgt = fmaxf(g_u[r] + vc, 0.f);
            float m = fminf(ZETA / (1.f + __expf(-wgt)), 1.f);
            mw = m * wgt;
            g_mw[p] = mw;
        }
        sum += mw;
    }
    sum = wred(sum);
    float d1 = rsqrtf(sum + 1.0f);
    if (lane == 0) g_dinv1[node] = d1;
    if (lane < 8) g_hws[node * 8 + lane] = d1 * g_hw[node * 8 + lane];
}

// ---------------- 8) conv1 ---------------------------------------------------
__global__ __launch_bounds__(256) void conv1_kernel(const float* __restrict__ b1,
                                                    float* __restrict__ out) {
    int warp = (blockIdx.x * blockDim.x + threadIdx.x) >> 5;
    int lane = threadIdx.x & 31;
    if (warp >= N_NODES) return;
    int node = warp;
    int s = g_off[node];
    int e = s + g_cnt[node];
    int g = lane >> 3;
    int f = lane & 7;

    float acc = (g == 0) ? g_hws[node * 8 + f] : 0.f;  // self term

    for (int p0 = s; p0 < e; p0 += 8) {
        int pA = p0 + g;
        int pB = p0 + 4 + g;
        int rA = (pA < e) ? g_src[pA] : -1;
        int rB = (pB < e) ? g_src[pB] : -1;
        float cA = (pA < e) ? g_mw[pA] : 0.f;
        float cB = (pB < e) ? g_mw[pB] : 0.f;
        if (rA >= 0) acc += cA * g_hws[rA * 8 + f];
        if (rB >= 0) acc += cB * g_hws[rB * 8 + f];
    }
    acc += __shfl_xor_sync(0xffffffffu, acc, 8);
    acc += __shfl_xor_sync(0xffffffffu, acc, 16);

    if (lane < 8)
        out[node * 8 + lane] = g_dinv1[node] * acc + __ldg(b1 + lane);
}

// ---------------- launch -----------------------------------------------------
extern "C" void kernel_launch(void* const* d_in, const int* in_sizes, int n_in,
                              void* d_out, int out_size) {
    const float* x     = (const float*)d_in[0];
    const int*   eidx  = (const int*)  d_in[1];
    const float* W0    = (const float*)d_in[2];
    const float* b0    = (const float*)d_in[3];
    const float* W1    = (const float*)d_in[4];
    const float* b1    = (const float*)d_in[5];
    const float* Wnb   = (const float*)d_in[6];
    const float* bnb   = (const float*)d_in[7];
    const float* Wself = (const float*)d_in[8];
    const float* bself = (const float*)d_in[9];
    const float* Watt  = (const float*)d_in[10];
    const float* batt  = (const float*)d_in[11];
    float* out = (float*)d_out;

    zero_prep<<<NB_SCAN, 1024>>>(W0, Wnb, bnb, Wself, bself, Watt, batt);     // 0
    count_kernel<<<(N_EDGES / 4 + 255) / 256, 256>>>(eidx);                   // 1
    scan_fused<<<NB_SCAN, 1024>>>();                                          // 2
    gemm_xw<<<(N_WARPS_GEMM * 32 + 255) / 256, 256>>>(x);                     // 3 (profiled)
    fill_kernel<<<(N_EDGES / 2 + 255) / 256, 256>>>(eidx);                    // 4
    conv0_kernel<<<(N_NODES * 32 + 255) / 256, 256>>>(b0, W1);                // 5
    attn_kernel<<<(N_NODES * 32 + 255) / 256, 256>>>();                       // 6
    conv1_kernel<<<(N_NODES * 32 + 255) / 256, 256>>>(b1, out);               // 7
}